// round 12
// baseline (speedup 1.0000x reference)
#include <cuda_runtime.h>
#include <cuda_fp16.h>
#include <cstdint>

#define B_    4
#define S_    2048
#define DIN   2048
#define DOUT  2048
#define M_TOT 8192
#define LK    128      // padded LoRA K (8 shared + 64 expert + 56 zero)
#define BM    128
#define BN    128
#define KSPLIT 4

// ------------------------- device scratch -------------------------
__device__ __half g_xh[M_TOT * DIN];     // fp16 x
__device__ __half g_Wh[DOUT * DIN];      // fp16 base_W
__device__ __half g_Aall[LK * DIN];      // rows: 8 shared_A, 64 expert_A, 56 zero
__device__ __half g_Wlora[DOUT * LK];    // [o][j]
__device__ __half g_T[M_TOT * LK];       // scaled low-rank activations
__device__ float  g_Tpart[KSPLIT * M_TOT * LK];  // split-K partials (16 MB)
__device__ float  g_meanpart[16 * B_ * DIN];
__device__ float  g_colscale[B_ * LK];

// ------------------------- helpers -------------------------
__device__ __forceinline__ uint32_t s2u(const void* p) {
    uint32_t a;
    asm("{ .reg .u64 t; cvta.to.shared.u64 t, %1; cvt.u32.u64 %0, t; }"
        : "=r"(a) : "l"(p));
    return a;
}

// ------------------------- prep kernels -------------------------
// blocks [0,512):     x -> fp16 + mean partials
// blocks [512,2560):  pack Aall / Wlora -> fp16
__global__ void prep_xpack(const float* __restrict__ x,
                           const float* __restrict__ sharedA,
                           const float* __restrict__ expertA,
                           const float* __restrict__ sharedB,
                           const float* __restrict__ expertB) {
    int bx = blockIdx.x;
    int tid = threadIdx.x;
    if (bx < 512) {
        int b  = bx >> 7;
        int sc = (bx >> 3) & 15;
        int dc = bx & 7;
        int d  = dc * 256 + tid;
        size_t off = ((size_t)b * S_ + sc * 128) * DIN + d;
        const float* p = x + off;
        __half* q = g_xh + off;
        float s = 0.f;
        #pragma unroll 4
        for (int i = 0; i < 128; i++) {
            float v = p[(size_t)i * DIN];
            s += v;
            q[(size_t)i * DIN] = __float2half_rn(v);
        }
        g_meanpart[(sc * B_ + b) * DIN + d] = s;
    } else {
        int i = (bx - 512) * 256 + tid;
        const int NA = LK * DIN;  // 262144
        if (i < NA) {
            int j = i / DIN, k = i % DIN;
            float v = 0.f;
            if (j < 8)        v = sharedA[j * DIN + k];
            else if (j < 72)  v = expertA[(j - 8) * DIN + k];
            g_Aall[i] = __float2half_rn(v);
        } else {
            int i2 = i - NA;
            int o = i2 / LK, j = i2 % LK;
            float v = 0.f;
            if (j < 8)        v = sharedB[o * 8 + j];
            else if (j < 72) { int e = (j - 8) >> 3, r = (j - 8) & 7;
                               v = expertB[((size_t)e * DOUT + o) * 8 + r]; }
            g_Wlora[i2] = __float2half_rn(v);
        }
    }
}

__global__ void prep_w(const float4* __restrict__ w) {
    int i = blockIdx.x * 256 + threadIdx.x;   // 1M float4 (DOUT*DIN/4)
    float4 v = w[i];
    __half2* o = (__half2*)g_Wh;
    o[i * 2]     = __floats2half2_rn(v.x, v.y);
    o[i * 2 + 1] = __floats2half2_rn(v.z, v.w);
}

// ------------------------- routing (with fused mean reduction) -------------
__global__ void routing_kernel(const float* __restrict__ task_emb,
                               const float* __restrict__ collab_w) {
    __shared__ float sxm[B_ * DIN];       // 32 KB: x_mean
    __shared__ float slog[B_][8];
    __shared__ float srout[B_][8];
    __shared__ float scw;
    int tid = threadIdx.x, lane = tid & 31, w = tid >> 5;  // warp w -> expert w

    for (int idx = tid; idx < B_ * DIN; idx += 256) {
        float s = 0.f;
        #pragma unroll
        for (int p = 0; p < 16; p++) s += g_meanpart[p * (B_ * DIN) + idx];
        sxm[idx] = s * (1.0f / (float)S_);
    }
    if (tid == 0) scw = 1.f / (1.f + expf(-collab_w[0]));
    __syncthreads();

    const float4* tev = (const float4*)(task_emb + w * DIN);
    for (int b = 0; b < B_; b++) {
        const float4* xv = (const float4*)(sxm + b * DIN);
        float p = 0.f;
        #pragma unroll 4
        for (int i = lane; i < DIN / 4; i += 32) {
            float4 a = xv[i], c = tev[i];
            p += a.x * c.x + a.y * c.y + a.z * c.z + a.w * c.w;
        }
        #pragma unroll
        for (int o = 16; o > 0; o >>= 1) p += __shfl_down_sync(0xffffffffu, p, o);
        if (lane == 0) slog[b][w] = p;
    }
    __syncthreads();
    if (tid < B_) {
        float mx = -1e30f;
        for (int e = 0; e < 8; e++) mx = fmaxf(mx, slog[tid][e]);
        float ex[8], sm = 0.f;
        for (int e = 0; e < 8; e++) { ex[e] = expf(slog[tid][e] - mx); sm += ex[e]; }
        for (int e = 0; e < 8; e++) srout[tid][e] = ex[e] / sm;
    }
    __syncthreads();
    float cw = scw;
    for (int i = tid; i < B_ * LK; i += 256) {
        int b = i / LK, j = i % LK;
        float v = 0.f;
        if (j < 8)       v = 2.0f * cw;
        else if (j < 72) v = 2.0f * (1.f - cw) * srout[b][(j - 8) >> 3];
        g_colscale[i] = v;
    }
}

// reduce split-K partials (float4), apply colscale, convert to fp16
__global__ void t_reduce() {
    int i4 = blockIdx.x * 256 + threadIdx.x;   // float4 index, 262144 total
    const int NP4 = M_TOT * LK / 4;
    const float4* P = (const float4*)g_Tpart;
    float4 a = P[i4], b = P[i4 + NP4], c = P[i4 + 2 * NP4], d = P[i4 + 3 * NP4];
    float s0 = a.x + b.x + c.x + d.x;
    float s1 = a.y + b.y + c.y + d.y;
    float s2 = a.z + b.z + c.z + d.z;
    float s3 = a.w + b.w + c.w + d.w;
    int i = i4 * 4;
    int j = i & (LK - 1);
    int bb = (i >> 7) >> 11;                   // batch of row m = i/128
    const float* cs = g_colscale + bb * LK + j;
    __half2* o = (__half2*)g_T;
    o[i4 * 2]     = __floats2half2_rn(s0 * cs[0], s1 * cs[1]);
    o[i4 * 2 + 1] = __floats2half2_rn(s2 * cs[2], s3 * cs[3]);
}

// ------------------------- fp16 mma.sync GEMM -------------------------
// CTA tile 128x128, 4 warps (2x2), warp tile 64x64, 2 CTAs/SM.
// BKH_: K halfs per stage; ROWB = 2*BKH_+16 bytes (conflict-free LDSM).
template<int BKH_, int NST_, int AHEAD,
         bool ADD_BIAS, bool SCALE_COLS, bool OUT_HALF, bool SPLITK>
__global__ void __launch_bounds__(128, 2)
gemm_h(const __half* __restrict__ A,  int lda,
       const __half* __restrict__ Bm, int ldb,
       const __half* __restrict__ A2, int lda2,
       const __half* __restrict__ B2, int ldb2,
       int kt1, int kt2,
       void* __restrict__ Cp, int ldc,
       const float* __restrict__ bias,
       const float* __restrict__ colscale)
{
    constexpr int JT    = 8;                  // mma n8 steps per warp (64 cols)
    constexpr int ROWB  = 2 * BKH_ + 16;      // bytes per smem row
    constexpr int GPR   = (2 * BKH_) / 16;    // 16B granules per row
    constexpr int GPT   = 256 * GPR / 128;    // granules per thread per stage
    constexpr int KSTEP = BKH_ / 16;          // k16 steps per stage
    extern __shared__ char sm[];

    const int tid  = threadIdx.x;
    const int bm   = blockIdx.y, bn = blockIdx.x;
    const int warp = tid >> 5, lane = tid & 31;
    const int wm   = warp >> 1, wn = warp & 1;   // 2x2 warps, 64x64 warp tile
    const int KT   = kt1 + kt2;

    if (SPLITK) {
        size_t koff = (size_t)blockIdx.z * kt1 * BKH_;
        A  += koff;  Bm += koff;
        Cp = (void*)((float*)Cp + (size_t)blockIdx.z * M_TOT * (size_t)ldc);
    }

    auto issue = [&](int kt, int slot) {
        const __half *a0, *b0; int la, lb;
        if (kt < kt1) { a0 = A;  b0 = Bm; la = lda;  lb = ldb;  }
        else          { a0 = A2; b0 = B2; la = lda2; lb = ldb2; kt -= kt1; }
        #pragma unroll
        for (int q = 0; q < GPT; q++) {
            int gid = q * 128 + tid;
            int row = gid / GPR, g = gid % GPR;
            uint32_t dst = s2u(sm + slot * 256 * ROWB + row * ROWB) + g * 16;
            const __half* src;
            if (row < BM) src = a0 + (size_t)(bm * BM + row) * la + kt * BKH_ + g * 8;
            else          src = b0 + (size_t)(bn * BN + row - BM) * lb + kt * BKH_ + g * 8;
            asm volatile("cp.async.cg.shared.global [%0], [%1], 16;\n"
                         :: "r"(dst), "l"(src));
        }
        asm volatile("cp.async.commit_group;\n");
    };

    float acc[4][JT][4];
    #pragma unroll
    for (int i = 0; i < 4; i++)
        #pragma unroll
        for (int j = 0; j < JT; j++)
            #pragma unroll
            for (int q = 0; q < 4; q++) acc[i][j][q] = 0.f;

    #pragma unroll
    for (int p = 0; p < AHEAD; p++) issue(p, p);

    const int a_row  = wm * 64 + (lane & 15);                 // + i*16
    const int a_coff = (lane >> 4) << 4;                      // 0 or 16 bytes
    const int b_row0 = BM + wn * 64 + (lane & 7) + ((lane >> 4) & 1) * 8;
    const int b_coff = ((lane >> 3) & 1) << 4;

    for (int kt = 0; kt < KT; ++kt) {
        int rem = KT - kt - 1;
        int allow = rem < AHEAD - 1 ? rem : AHEAD - 1;
        if (allow == 3)      asm volatile("cp.async.wait_group 3;\n");
        else if (allow == 2) asm volatile("cp.async.wait_group 2;\n");
        else if (allow == 1) asm volatile("cp.async.wait_group 1;\n");
        else                 asm volatile("cp.async.wait_group 0;\n");
        __syncthreads();
        if (kt + AHEAD < KT) issue(kt + AHEAD, (kt + AHEAD) % NST_);

        int slot = kt % NST_;
        uint32_t base = s2u(sm + slot * 256 * ROWB);

        #pragma unroll
        for (int ks = 0; ks < KSTEP; ks++) {
            uint32_t af[4][4], bf[JT][2];
            #pragma unroll
            for (int i = 0; i < 4; i++) {
                uint32_t addr = base + (uint32_t)(a_row + i * 16) * ROWB
                              + (uint32_t)(ks * 32 + a_coff);
                asm volatile(
                    "ldmatrix.sync.aligned.m8n8.x4.shared.b16 {%0,%1,%2,%3}, [%4];"
                    : "=r"(af[i][0]), "=r"(af[i][1]), "=r"(af[i][2]), "=r"(af[i][3])
                    : "r"(addr));
            }
            #pragma unroll
            for (int jn = 0; jn < JT / 2; jn++) {
                uint32_t r0, r1, r2, r3;
                uint32_t addr = base + (uint32_t)(b_row0 + jn * 16) * ROWB
                              + (uint32_t)(ks * 32 + b_coff);
                asm volatile(
                    "ldmatrix.sync.aligned.m8n8.x4.shared.b16 {%0,%1,%2,%3}, [%4];"
                    : "=r"(r0), "=r"(r1), "=r"(r2), "=r"(r3)
                    : "r"(addr));
                bf[jn * 2][0] = r0;     bf[jn * 2][1] = r1;
                bf[jn * 2 + 1][0] = r2; bf[jn * 2 + 1][1] = r3;
            }
            #pragma unroll
            for (int i = 0; i < 4; i++)
                #pragma unroll
                for (int j = 0; j < JT; j++) {
                    asm volatile(
                        "mma.sync.aligned.m16n8k16.row.col.f32.f16.f16.f32 "
                        "{%0,%1,%2,%3}, {%4,%5,%6,%7}, {%8,%9}, {%0,%1,%2,%3};\n"
                        : "+f"(acc[i][j][0]), "+f"(acc[i][j][1]),
                          "+f"(acc[i][j][2]), "+f"(acc[i][j][3])
                        : "r"(af[i][0]), "r"(af[i][1]), "r"(af[i][2]), "r"(af[i][3]),
                          "r"(bf[j][0]), "r"(bf[j][1]));
                }
        }
    }

    // ---- epilogue ----
    const int g = lane >> 2, tg = lane & 3;
    #pragma unroll
    for (int i = 0; i < 4; i++) {
        int m0 = bm * BM + wm * 64 + i * 16 + g;
        #pragma unroll
        for (int j = 0; j < JT; j++) {
            int n0 = bn * BN + wn * 64 + j * 8 + tg * 2;
            float c0 = acc[i][j][0], c1 = acc[i][j][1];
            float c2 = acc[i][j][2], c3 = acc[i][j][3];
            if (ADD_BIAS) {
                float b0v = bias[n0], b1v = bias[n0 + 1];
                c0 += b0v; c1 += b1v; c2 += b0v; c3 += b1v;
            }
            if (SCALE_COLS) {
                int bidx = m0 >> 11;   // 2048 rows per batch
                float s0 = colscale[bidx * LK + n0], s1 = colscale[bidx * LK + n0 + 1];
                c0 *= s0; c1 *= s1; c2 *= s0; c3 *= s1;
            }
            if (OUT_HALF) {
                __half2* C = (__half2*)Cp;
                C[((size_t)m0 * ldc + n0) >> 1]       = __floats2half2_rn(c0, c1);
                C[((size_t)(m0 + 8) * ldc + n0) >> 1] = __floats2half2_rn(c2, c3);
            } else {
                float* C = (float*)Cp;
                *(float2*)&C[(size_t)m0 * ldc + n0]       = make_float2(c0, c1);
                *(float2*)&C[(size_t)(m0 + 8) * ldc + n0] = make_float2(c2, c3);
            }
        }
    }
}

// ------------------------- host -------------------------
extern "C" void kernel_launch(void* const* d_in, const int* in_sizes, int n_in,
                              void* d_out, int out_size) {
    const float* x        = (const float*)d_in[0];
    const float* base_W   = (const float*)d_in[1];
    const float* base_b   = (const float*)d_in[2];
    const float* shared_A = (const float*)d_in[3];
    const float* shared_B = (const float*)d_in[4];
    const float* expert_A = (const float*)d_in[5];
    const float* expert_B = (const float*)d_in[6];
    const float* task_emb = (const float*)d_in[7];
    const float* collab_w = (const float*)d_in[8];
    float* out = (float*)d_out;
    (void)in_sizes; (void)n_in; (void)out_size;

    void *pXh, *pWh, *pAall, *pWlora, *pT, *pTp;
    cudaGetSymbolAddress(&pXh,    g_xh);
    cudaGetSymbolAddress(&pWh,    g_Wh);
    cudaGetSymbolAddress(&pAall,  g_Aall);
    cudaGetSymbolAddress(&pWlora, g_Wlora);
    cudaGetSymbolAddress(&pT,     g_T);
    cudaGetSymbolAddress(&pTp,    g_Tpart);

    // main: BKH=32, NST=5 -> 102400 B ; T: BKH=64, NST=3 -> 110592 B
    const int SMEM_MAIN = 5 * 256 * 80;
    const int SMEM_T    = 3 * 256 * 144;
    cudaFuncSetAttribute((const void*)gemm_h<64, 3, 2, false, false, false, true>,
                         cudaFuncAttributeMaxDynamicSharedMemorySize, SMEM_T);
    cudaFuncSetAttribute((const void*)gemm_h<32, 5, 4, true,  false, false, false>,
                         cudaFuncAttributeMaxDynamicSharedMemorySize, SMEM_MAIN);

    // side stream for prep_w (independent of x/pack/routing/T chain)
    cudaStream_t s2;
    cudaStreamCreateWithFlags(&s2, cudaStreamNonBlocking);
    cudaEvent_t e0, e2;
    cudaEventCreateWithFlags(&e0, cudaEventDisableTiming);
    cudaEventCreateWithFlags(&e2, cudaEventDisableTiming);

    // fork: prep_w on s2
    cudaEventRecord(e0, 0);
    cudaStreamWaitEvent(s2, e0, 0);
    prep_w<<<(DOUT * DIN) / (4 * 256), 256, 0, s2>>>((const float4*)base_W);
    cudaEventRecord(e2, s2);

    // main chain on default stream
    prep_xpack<<<2560, 256>>>(x, shared_A, expert_A, shared_B, expert_B);
    routing_kernel<<<1, 256>>>(task_emb, collab_w);

    // T partials: x @ Aall^T split-K x4 : M=8192, N=128, K=512 per split
    gemm_h<64, 3, 2, false, false, false, true>
        <<<dim3(1, M_TOT / BM, KSPLIT), 128, SMEM_T>>>(
        (const __half*)pXh, DIN, (const __half*)pAall, DIN,
        (const __half*)pXh, DIN, (const __half*)pAall, DIN,   // unused segment 2
        (DIN / 64) / KSPLIT, 0,
        pTp, LK, nullptr, nullptr);

    // reduce + colscale + fp16 convert
    t_reduce<<<(M_TOT * LK / 4) / 256, 256>>>();

    // join: main GEMM needs g_Wh
    cudaStreamWaitEvent(0, e2, 0);

    // out = x @ W^T + b + T' @ Wlora^T : M=8192, N=2048, K=2048+128
    gemm_h<32, 5, 4, true, false, false, false>
        <<<dim3(DOUT / BN, M_TOT / BM), 128, SMEM_MAIN>>>(
        (const __half*)pXh, DIN, (const __half*)pWh, DIN,
        (const __half*)pT,  LK,  (const __half*)pWlora, LK,
        DIN / 32, LK / 32,
        out, DOUT, (const float*)base_b, nullptr);
    // note: s2/e0/e2 intentionally not destroyed here — destroying objects
    // used by an in-progress stream capture invalidates the capture; the
    // handful of leaked host-side objects across the harness's few
    // kernel_launch calls is bounded and allocation-rule-safe.
}

// round 13
// speedup vs baseline: 1.0673x; 1.0673x over previous
#include <cuda_runtime.h>
#include <cuda_fp16.h>
#include <cstdint>

#define B_    4
#define S_    2048
#define DIN   2048
#define DOUT  2048
#define M_TOT 8192
#define LK    128      // padded LoRA K (8 shared + 64 expert + 56 zero)
#define BM    128
#define BN    128
#define KSPLIT 4

// ------------------------- device scratch -------------------------
__device__ __half g_xh[M_TOT * DIN];     // fp16 x
__device__ __half g_Wh[DOUT * DIN];      // fp16 base_W
__device__ __half g_Aall[LK * DIN];      // rows: 8 shared_A, 64 expert_A, 56 zero
__device__ __half g_Wlora[DOUT * LK];    // [o][j]
__device__ __half g_T[M_TOT * LK];       // scaled low-rank activations
__device__ float  g_Tpart[KSPLIT * M_TOT * LK];  // split-K partials (16 MB)
__device__ float  g_meanpart[16 * B_ * DIN];
__device__ float  g_colscale[B_ * LK];

// ------------------------- helpers -------------------------
__device__ __forceinline__ uint32_t s2u(const void* p) {
    uint32_t a;
    asm("{ .reg .u64 t; cvta.to.shared.u64 t, %1; cvt.u32.u64 %0, t; }"
        : "=r"(a) : "l"(p));
    return a;
}

// ------------------------- prep kernels -------------------------
// blocks [0,512):     x -> fp16 + mean partials
// blocks [512,2560):  pack Aall / Wlora -> fp16
__global__ void prep_xpack(const float* __restrict__ x,
                           const float* __restrict__ sharedA,
                           const float* __restrict__ expertA,
                           const float* __restrict__ sharedB,
                           const float* __restrict__ expertB) {
    int bx = blockIdx.x;
    int tid = threadIdx.x;
    if (bx < 512) {
        int b  = bx >> 7;
        int sc = (bx >> 3) & 15;
        int dc = bx & 7;
        int d  = dc * 256 + tid;
        size_t off = ((size_t)b * S_ + sc * 128) * DIN + d;
        const float* p = x + off;
        __half* q = g_xh + off;
        float s = 0.f;
        #pragma unroll 4
        for (int i = 0; i < 128; i++) {
            float v = p[(size_t)i * DIN];
            s += v;
            q[(size_t)i * DIN] = __float2half_rn(v);
        }
        g_meanpart[(sc * B_ + b) * DIN + d] = s;
    } else {
        int i = (bx - 512) * 256 + tid;
        const int NA = LK * DIN;  // 262144
        if (i < NA) {
            int j = i / DIN, k = i % DIN;
            float v = 0.f;
            if (j < 8)        v = sharedA[j * DIN + k];
            else if (j < 72)  v = expertA[(j - 8) * DIN + k];
            g_Aall[i] = __float2half_rn(v);
        } else {
            int i2 = i - NA;
            int o = i2 / LK, j = i2 % LK;
            float v = 0.f;
            if (j < 8)        v = sharedB[o * 8 + j];
            else if (j < 72) { int e = (j - 8) >> 3, r = (j - 8) & 7;
                               v = expertB[((size_t)e * DOUT + o) * 8 + r]; }
            g_Wlora[i2] = __float2half_rn(v);
        }
    }
}

__global__ void prep_w(const float4* __restrict__ w) {
    int i = blockIdx.x * 256 + threadIdx.x;   // 1M float4 (DOUT*DIN/4)
    float4 v = w[i];
    __half2* o = (__half2*)g_Wh;
    o[i * 2]     = __floats2half2_rn(v.x, v.y);
    o[i * 2 + 1] = __floats2half2_rn(v.z, v.w);
}

// ------------------------- routing (with fused mean reduction) -------------
__global__ void routing_kernel(const float* __restrict__ task_emb,
                               const float* __restrict__ collab_w) {
    __shared__ float sxm[B_ * DIN];       // 32 KB: x_mean
    __shared__ float slog[B_][8];
    __shared__ float srout[B_][8];
    __shared__ float scw;
    int tid = threadIdx.x, lane = tid & 31, w = tid >> 5;  // warp w -> expert w

    for (int idx = tid; idx < B_ * DIN; idx += 256) {
        float s = 0.f;
        #pragma unroll
        for (int p = 0; p < 16; p++) s += g_meanpart[p * (B_ * DIN) + idx];
        sxm[idx] = s * (1.0f / (float)S_);
    }
    if (tid == 0) scw = 1.f / (1.f + expf(-collab_w[0]));
    __syncthreads();

    const float4* tev = (const float4*)(task_emb + w * DIN);
    for (int b = 0; b < B_; b++) {
        const float4* xv = (const float4*)(sxm + b * DIN);
        float p = 0.f;
        #pragma unroll 4
        for (int i = lane; i < DIN / 4; i += 32) {
            float4 a = xv[i], c = tev[i];
            p += a.x * c.x + a.y * c.y + a.z * c.z + a.w * c.w;
        }
        #pragma unroll
        for (int o = 16; o > 0; o >>= 1) p += __shfl_down_sync(0xffffffffu, p, o);
        if (lane == 0) slog[b][w] = p;
    }
    __syncthreads();
    if (tid < B_) {
        float mx = -1e30f;
        for (int e = 0; e < 8; e++) mx = fmaxf(mx, slog[tid][e]);
        float ex[8], sm = 0.f;
        for (int e = 0; e < 8; e++) { ex[e] = expf(slog[tid][e] - mx); sm += ex[e]; }
        for (int e = 0; e < 8; e++) srout[tid][e] = ex[e] / sm;
    }
    __syncthreads();
    float cw = scw;
    for (int i = tid; i < B_ * LK; i += 256) {
        int b = i / LK, j = i % LK;
        float v = 0.f;
        if (j < 8)       v = 2.0f * cw;
        else if (j < 72) v = 2.0f * (1.f - cw) * srout[b][(j - 8) >> 3];
        g_colscale[i] = v;
    }
}

// reduce split-K partials, apply colscale, convert to fp16.
// 2 float4-groups per thread, all loads issued up front for MLP.
__global__ void t_reduce() {
    const int NP4 = M_TOT * LK / 4;            // 262144
    const int HALF = NP4 / 2;                  // 131072
    int i4a = blockIdx.x * 256 + threadIdx.x;  // 0 .. HALF-1 (grid 512)
    int i4b = i4a + HALF;
    const float4* P = (const float4*)g_Tpart;
    float4 a0 = P[i4a], b0 = P[i4a + NP4], c0 = P[i4a + 2 * NP4], d0 = P[i4a + 3 * NP4];
    float4 a1 = P[i4b], b1 = P[i4b + NP4], c1 = P[i4b + 2 * NP4], d1 = P[i4b + 3 * NP4];
    __half2* o = (__half2*)g_T;
    {
        float s0 = a0.x + b0.x + c0.x + d0.x;
        float s1 = a0.y + b0.y + c0.y + d0.y;
        float s2 = a0.z + b0.z + c0.z + d0.z;
        float s3 = a0.w + b0.w + c0.w + d0.w;
        int i = i4a * 4;
        int j = i & (LK - 1);
        int bb = i >> 18;                       // batch of row m = i/128 (2048 rows/batch)
        const float* cs = g_colscale + bb * LK + j;
        o[i4a * 2]     = __floats2half2_rn(s0 * cs[0], s1 * cs[1]);
        o[i4a * 2 + 1] = __floats2half2_rn(s2 * cs[2], s3 * cs[3]);
    }
    {
        float s0 = a1.x + b1.x + c1.x + d1.x;
        float s1 = a1.y + b1.y + c1.y + d1.y;
        float s2 = a1.z + b1.z + c1.z + d1.z;
        float s3 = a1.w + b1.w + c1.w + d1.w;
        int i = i4b * 4;
        int j = i & (LK - 1);
        int bb = i >> 18;
        const float* cs = g_colscale + bb * LK + j;
        o[i4b * 2]     = __floats2half2_rn(s0 * cs[0], s1 * cs[1]);
        o[i4b * 2 + 1] = __floats2half2_rn(s2 * cs[2], s3 * cs[3]);
    }
}

// ------------------------- fp16 mma.sync GEMM -------------------------
// CTA tile 128x128, 4 warps (2x2), warp tile 64x64, 2 CTAs/SM.
// BKH_: K halfs per stage; ROWB = 2*BKH_+16 bytes (conflict-free LDSM).
template<int BKH_, int NST_, int AHEAD,
         bool ADD_BIAS, bool SCALE_COLS, bool OUT_HALF, bool SPLITK>
__global__ void __launch_bounds__(128, 2)
gemm_h(const __half* __restrict__ A,  int lda,
       const __half* __restrict__ Bm, int ldb,
       const __half* __restrict__ A2, int lda2,
       const __half* __restrict__ B2, int ldb2,
       int kt1, int kt2,
       void* __restrict__ Cp, int ldc,
       const float* __restrict__ bias,
       const float* __restrict__ colscale)
{
    constexpr int JT    = 8;                  // mma n8 steps per warp (64 cols)
    constexpr int ROWB  = 2 * BKH_ + 16;      // bytes per smem row
    constexpr int GPR   = (2 * BKH_) / 16;    // 16B granules per row
    constexpr int GPT   = 256 * GPR / 128;    // granules per thread per stage
    constexpr int KSTEP = BKH_ / 16;          // k16 steps per stage
    extern __shared__ char sm[];

    const int tid  = threadIdx.x;
    const int bm   = blockIdx.y, bn = blockIdx.x;
    const int warp = tid >> 5, lane = tid & 31;
    const int wm   = warp >> 1, wn = warp & 1;   // 2x2 warps, 64x64 warp tile
    const int KT   = kt1 + kt2;

    if (SPLITK) {
        size_t koff = (size_t)blockIdx.z * kt1 * BKH_;
        A  += koff;  Bm += koff;
        Cp = (void*)((float*)Cp + (size_t)blockIdx.z * M_TOT * (size_t)ldc);
    }

    auto issue = [&](int kt, int slot) {
        const __half *a0, *b0; int la, lb;
        if (kt < kt1) { a0 = A;  b0 = Bm; la = lda;  lb = ldb;  }
        else          { a0 = A2; b0 = B2; la = lda2; lb = ldb2; kt -= kt1; }
        #pragma unroll
        for (int q = 0; q < GPT; q++) {
            int gid = q * 128 + tid;
            int row = gid / GPR, g = gid % GPR;
            uint32_t dst = s2u(sm + slot * 256 * ROWB + row * ROWB) + g * 16;
            const __half* src;
            if (row < BM) src = a0 + (size_t)(bm * BM + row) * la + kt * BKH_ + g * 8;
            else          src = b0 + (size_t)(bn * BN + row - BM) * lb + kt * BKH_ + g * 8;
            asm volatile("cp.async.cg.shared.global [%0], [%1], 16;\n"
                         :: "r"(dst), "l"(src));
        }
        asm volatile("cp.async.commit_group;\n");
    };

    float acc[4][JT][4];
    #pragma unroll
    for (int i = 0; i < 4; i++)
        #pragma unroll
        for (int j = 0; j < JT; j++)
            #pragma unroll
            for (int q = 0; q < 4; q++) acc[i][j][q] = 0.f;

    #pragma unroll
    for (int p = 0; p < AHEAD; p++) issue(p, p);

    const int a_row  = wm * 64 + (lane & 15);                 // + i*16
    const int a_coff = (lane >> 4) << 4;                      // 0 or 16 bytes
    const int b_row0 = BM + wn * 64 + (lane & 7) + ((lane >> 4) & 1) * 8;
    const int b_coff = ((lane >> 3) & 1) << 4;

    for (int kt = 0; kt < KT; ++kt) {
        int rem = KT - kt - 1;
        int allow = rem < AHEAD - 1 ? rem : AHEAD - 1;
        if (allow == 3)      asm volatile("cp.async.wait_group 3;\n");
        else if (allow == 2) asm volatile("cp.async.wait_group 2;\n");
        else if (allow == 1) asm volatile("cp.async.wait_group 1;\n");
        else                 asm volatile("cp.async.wait_group 0;\n");
        __syncthreads();
        if (kt + AHEAD < KT) issue(kt + AHEAD, (kt + AHEAD) % NST_);

        int slot = kt % NST_;
        uint32_t base = s2u(sm + slot * 256 * ROWB);

        #pragma unroll
        for (int ks = 0; ks < KSTEP; ks++) {
            uint32_t af[4][4], bf[JT][2];
            #pragma unroll
            for (int i = 0; i < 4; i++) {
                uint32_t addr = base + (uint32_t)(a_row + i * 16) * ROWB
                              + (uint32_t)(ks * 32 + a_coff);
                asm volatile(
                    "ldmatrix.sync.aligned.m8n8.x4.shared.b16 {%0,%1,%2,%3}, [%4];"
                    : "=r"(af[i][0]), "=r"(af[i][1]), "=r"(af[i][2]), "=r"(af[i][3])
                    : "r"(addr));
            }
            #pragma unroll
            for (int jn = 0; jn < JT / 2; jn++) {
                uint32_t r0, r1, r2, r3;
                uint32_t addr = base + (uint32_t)(b_row0 + jn * 16) * ROWB
                              + (uint32_t)(ks * 32 + b_coff);
                asm volatile(
                    "ldmatrix.sync.aligned.m8n8.x4.shared.b16 {%0,%1,%2,%3}, [%4];"
                    : "=r"(r0), "=r"(r1), "=r"(r2), "=r"(r3)
                    : "r"(addr));
                bf[jn * 2][0] = r0;     bf[jn * 2][1] = r1;
                bf[jn * 2 + 1][0] = r2; bf[jn * 2 + 1][1] = r3;
            }
            #pragma unroll
            for (int i = 0; i < 4; i++)
                #pragma unroll
                for (int j = 0; j < JT; j++) {
                    asm volatile(
                        "mma.sync.aligned.m16n8k16.row.col.f32.f16.f16.f32 "
                        "{%0,%1,%2,%3}, {%4,%5,%6,%7}, {%8,%9}, {%0,%1,%2,%3};\n"
                        : "+f"(acc[i][j][0]), "+f"(acc[i][j][1]),
                          "+f"(acc[i][j][2]), "+f"(acc[i][j][3])
                        : "r"(af[i][0]), "r"(af[i][1]), "r"(af[i][2]), "r"(af[i][3]),
                          "r"(bf[j][0]), "r"(bf[j][1]));
                }
        }
    }

    // ---- epilogue ----
    const int g = lane >> 2, tg = lane & 3;
    #pragma unroll
    for (int i = 0; i < 4; i++) {
        int m0 = bm * BM + wm * 64 + i * 16 + g;
        #pragma unroll
        for (int j = 0; j < JT; j++) {
            int n0 = bn * BN + wn * 64 + j * 8 + tg * 2;
            float c0 = acc[i][j][0], c1 = acc[i][j][1];
            float c2 = acc[i][j][2], c3 = acc[i][j][3];
            if (ADD_BIAS) {
                float b0v = bias[n0], b1v = bias[n0 + 1];
                c0 += b0v; c1 += b1v; c2 += b0v; c3 += b1v;
            }
            if (SCALE_COLS) {
                int bidx = m0 >> 11;   // 2048 rows per batch
                float s0 = colscale[bidx * LK + n0], s1 = colscale[bidx * LK + n0 + 1];
                c0 *= s0; c1 *= s1; c2 *= s0; c3 *= s1;
            }
            if (OUT_HALF) {
                __half2* C = (__half2*)Cp;
                C[((size_t)m0 * ldc + n0) >> 1]       = __floats2half2_rn(c0, c1);
                C[((size_t)(m0 + 8) * ldc + n0) >> 1] = __floats2half2_rn(c2, c3);
            } else {
                float* C = (float*)Cp;
                *(float2*)&C[(size_t)m0 * ldc + n0]       = make_float2(c0, c1);
                *(float2*)&C[(size_t)(m0 + 8) * ldc + n0] = make_float2(c2, c3);
            }
        }
    }
}

// ------------------------- host -------------------------
extern "C" void kernel_launch(void* const* d_in, const int* in_sizes, int n_in,
                              void* d_out, int out_size) {
    const float* x        = (const float*)d_in[0];
    const float* base_W   = (const float*)d_in[1];
    const float* base_b   = (const float*)d_in[2];
    const float* shared_A = (const float*)d_in[3];
    const float* shared_B = (const float*)d_in[4];
    const float* expert_A = (const float*)d_in[5];
    const float* expert_B = (const float*)d_in[6];
    const float* task_emb = (const float*)d_in[7];
    const float* collab_w = (const float*)d_in[8];
    float* out = (float*)d_out;
    (void)in_sizes; (void)n_in; (void)out_size;

    void *pXh, *pWh, *pAall, *pWlora, *pT, *pTp;
    cudaGetSymbolAddress(&pXh,    g_xh);
    cudaGetSymbolAddress(&pWh,    g_Wh);
    cudaGetSymbolAddress(&pAall,  g_Aall);
    cudaGetSymbolAddress(&pWlora, g_Wlora);
    cudaGetSymbolAddress(&pT,     g_T);
    cudaGetSymbolAddress(&pTp,    g_Tpart);

    // main: BKH=32, NST=5 -> 102400 B ; T: BKH=64, NST=3 -> 110592 B
    const int SMEM_MAIN = 5 * 256 * 80;
    const int SMEM_T    = 3 * 256 * 144;
    cudaFuncSetAttribute((const void*)gemm_h<64, 3, 2, false, false, false, true>,
                         cudaFuncAttributeMaxDynamicSharedMemorySize, SMEM_T);
    cudaFuncSetAttribute((const void*)gemm_h<32, 5, 4, true,  false, false, false>,
                         cudaFuncAttributeMaxDynamicSharedMemorySize, SMEM_MAIN);

    // side stream: prep_w, then routing (after prep_xpack) — both independent
    // of the T-GEMM, which they overlap.
    cudaStream_t s2;
    cudaStreamCreateWithFlags(&s2, cudaStreamNonBlocking);
    cudaEvent_t e0, e1, e3;
    cudaEventCreateWithFlags(&e0, cudaEventDisableTiming);
    cudaEventCreateWithFlags(&e1, cudaEventDisableTiming);
    cudaEventCreateWithFlags(&e3, cudaEventDisableTiming);

    // fork: prep_w on s2 (no deps)
    cudaEventRecord(e0, 0);
    cudaStreamWaitEvent(s2, e0, 0);
    prep_w<<<(DOUT * DIN) / (4 * 256), 256, 0, s2>>>((const float4*)base_W);

    // stream 0: x/pack prep
    prep_xpack<<<2560, 256>>>(x, shared_A, expert_A, shared_B, expert_B);
    cudaEventRecord(e1, 0);

    // routing on s2 (needs g_meanpart from prep_xpack); overlaps T-GEMM
    cudaStreamWaitEvent(s2, e1, 0);
    routing_kernel<<<1, 256, 0, s2>>>(task_emb, collab_w);
    cudaEventRecord(e3, s2);

    // T partials: x @ Aall^T split-K x4 : M=8192, N=128, K=512 per split
    gemm_h<64, 3, 2, false, false, false, true>
        <<<dim3(1, M_TOT / BM, KSPLIT), 128, SMEM_T>>>(
        (const __half*)pXh, DIN, (const __half*)pAall, DIN,
        (const __half*)pXh, DIN, (const __half*)pAall, DIN,   // unused segment 2
        (DIN / 64) / KSPLIT, 0,
        pTp, LK, nullptr, nullptr);

    // join: t_reduce needs colscale (routing) + partials (T-GEMM);
    // e3 also transitively covers prep_w for the main GEMM below.
    cudaStreamWaitEvent(0, e3, 0);
    t_reduce<<<512, 256>>>();

    // out = x @ W^T + b + T' @ Wlora^T : M=8192, N=2048, K=2048+128
    gemm_h<32, 5, 4, true, false, false, false>
        <<<dim3(DOUT / BN, M_TOT / BM), 128, SMEM_MAIN>>>(
        (const __half*)pXh, DIN, (const __half*)pWh, DIN,
        (const __half*)pT,  LK,  (const __half*)pWlora, LK,
        DIN / 32, LK / 32,
        out, DOUT, (const float*)base_b, nullptr);
    // note: s2/e0/e1/e3 intentionally not destroyed — destroying objects used
    // by an in-progress stream capture invalidates the capture; the bounded
    // handful of leaked host-side objects is allocation-rule-safe.
}